// round 1
// baseline (speedup 1.0000x reference)
#include <cuda_runtime.h>

// ---------------- problem constants ----------------
#define NB   32
#define SEQ  1024
#define NF   512
#define NCH  19      // 19 chunks -> grid 32*19 = 608 = 4*152 SMs (perfect balance)
#define CLEN 54      // chunks 0..17 have 54 steps, chunk 18 has 52
#define MU_C 10.0f
// loglik2 = -MU*T*(2*pi)^(D-1) = -100 * (2pi)^2
#define LOGLIK2 (-3947.8417604357434f)

typedef unsigned long long ull;

// ---------------- scratch (__device__ globals: no allocation) ----------------
__device__ float g_womg[3 * NF];          // Womg[d][n]
__device__ ull   g_sums[NB * NCH * NF];   // packed (sumC, sumS) per (b, chunk, n); after scan: exclusive base

// ---------------- f32x2 packed helpers (sm_103a) ----------------
static __device__ __forceinline__ ull pk2(float lo, float hi) {
    ull r; asm("mov.b64 %0, {%1, %2};" : "=l"(r) : "f"(lo), "f"(hi)); return r;
}
static __device__ __forceinline__ void up2(ull v, float& lo, float& hi) {
    asm("mov.b64 {%0, %1}, %2;" : "=f"(lo), "=f"(hi) : "l"(v));
}
static __device__ __forceinline__ ull fma2(ull a, ull b, ull c) {
    ull r; asm("fma.rn.f32x2 %0, %1, %2, %3;" : "=l"(r) : "l"(a), "l"(b), "l"(c)); return r;
}
static __device__ __forceinline__ ull mul2(ull a, ull b) {
    ull r; asm("mul.rn.f32x2 %0, %1, %2;" : "=l"(r) : "l"(a), "l"(b)); return r;
}
static __device__ __forceinline__ ull add2(ull a, ull b) {
    ull r; asm("add.rn.f32x2 %0, %1, %2;" : "=l"(r) : "l"(a), "l"(b)); return r;
}
static __device__ __forceinline__ float fsin(float x) {
    float r; asm("sin.approx.f32 %0, %1;" : "=f"(r) : "f"(x)); return r;
}
static __device__ __forceinline__ float fcos(float x) {
    float r; asm("cos.approx.f32 %0, %1;" : "=f"(r) : "f"(x)); return r;
}

// ---------------- Kernel A: fourier MLP -> Womg[3][512] ----------------
// grid 512 (one block per fourier sample n), 128 threads
__global__ void __launch_bounds__(128) mlp_womg(
    const float* __restrict__ noise,  // [512,64]
    const float* __restrict__ W1,     // [64,100]
    const float* __restrict__ b1,     // [100]
    const float* __restrict__ W2,     // [100,256]
    const float* __restrict__ b2,     // [256]
    const float* __restrict__ Wm)     // [256,3]
{
    __shared__ float sn[64];
    __shared__ float sh[100];
    __shared__ float wp[4][3];
    const int n = blockIdx.x;
    const int t = threadIdx.x;

    if (t < 64) sn[t] = noise[n * 64 + t];
    __syncthreads();

    if (t < 100) {
        float a = b1[t];
#pragma unroll 8
        for (int k = 0; k < 64; k++) a += sn[k] * W1[k * 100 + t];
        sh[t] = tanhf(a);
    }
    __syncthreads();

    // fourier features for columns t and t+128
    float a0 = b2[t], a1 = b2[t + 128];
#pragma unroll 4
    for (int h = 0; h < 100; h++) {
        const float hv = sh[h];
        a0 += hv * W2[h * 256 + t];
        a1 += hv * W2[h * 256 + t + 128];
    }
    const float f0 = tanhf(a0);
    const float f1 = tanhf(a1);

    float pd0 = f0 * Wm[t * 3 + 0] + f1 * Wm[(t + 128) * 3 + 0];
    float pd1 = f0 * Wm[t * 3 + 1] + f1 * Wm[(t + 128) * 3 + 1];
    float pd2 = f0 * Wm[t * 3 + 2] + f1 * Wm[(t + 128) * 3 + 2];
#pragma unroll
    for (int o = 16; o > 0; o >>= 1) {
        pd0 += __shfl_xor_sync(0xffffffffu, pd0, o);
        pd1 += __shfl_xor_sync(0xffffffffu, pd1, o);
        pd2 += __shfl_xor_sync(0xffffffffu, pd2, o);
    }
    if ((t & 31) == 0) { wp[t >> 5][0] = pd0; wp[t >> 5][1] = pd1; wp[t >> 5][2] = pd2; }
    __syncthreads();
    if (t == 0) {
#pragma unroll
        for (int d = 0; d < 3; d++)
            g_womg[d * NF + n] = wp[0][d] + wp[1][d] + wp[2][d] + wp[3][d];
    }
}

// ---------------- Kernel B: per-chunk (sumC, sumS) ----------------
// grid NB*NCH = 608, 128 threads, thread owns n in {t, t+128, t+256, t+384}
__global__ void __launch_bounds__(128) chunk_sums(const float* __restrict__ X)
{
    __shared__ float4 sx[CLEN];
    const int bx = blockIdx.x;
    const int b = bx / NCH;
    const int ch = bx - b * NCH;
    const int i0 = ch * CLEN;
    const int clen = (ch == NCH - 1) ? (SEQ - i0) : CLEN;
    const int t = threadIdx.x;

    if (t < clen) {
        const float* xp = X + (size_t)(b * SEQ + i0 + t) * 3;
        sx[t] = make_float4(xp[0], xp[1], xp[2], 0.f);
    }
    // womg pairs: AC = (n=t, n=t+256), BD = (n=t+128, n=t+384)
    const ull w0AC = pk2(g_womg[0 * NF + t], g_womg[0 * NF + t + 256]);
    const ull w1AC = pk2(g_womg[1 * NF + t], g_womg[1 * NF + t + 256]);
    const ull w2AC = pk2(g_womg[2 * NF + t], g_womg[2 * NF + t + 256]);
    const ull w0BD = pk2(g_womg[0 * NF + t + 128], g_womg[0 * NF + t + 384]);
    const ull w1BD = pk2(g_womg[1 * NF + t + 128], g_womg[1 * NF + t + 384]);
    const ull w2BD = pk2(g_womg[2 * NF + t + 128], g_womg[2 * NF + t + 384]);
    __syncthreads();

    ull cA = 0ull, cB = 0ull, cC = 0ull, cD = 0ull;  // packed (sumC, sumS)
#pragma unroll 2
    for (int i = 0; i < clen; i++) {
        const float4 x = sx[i];
        const ull x0 = pk2(x.x, x.x), x1 = pk2(x.y, x.y), x2 = pk2(x.z, x.z);
        const ull thAC = fma2(x2, w2AC, fma2(x1, w1AC, mul2(x0, w0AC)));
        const ull thBD = fma2(x2, w2BD, fma2(x1, w1BD, mul2(x0, w0BD)));
        float tA, tC, tB, tD;
        up2(thAC, tA, tC);
        up2(thBD, tB, tD);
        cA = add2(cA, pk2(fcos(tA), fsin(tA)));
        cB = add2(cB, pk2(fcos(tB), fsin(tB)));
        cC = add2(cC, pk2(fcos(tC), fsin(tC)));
        cD = add2(cD, pk2(fcos(tD), fsin(tD)));
    }
    ull* o = g_sums + (size_t)(b * NCH + ch) * NF;
    o[t]       = cA;
    o[t + 128] = cB;
    o[t + 256] = cC;
    o[t + 384] = cD;
}

// ---------------- Kernel C: exclusive scan over chunks + loglik tail ----------------
// grid NB, 512 threads (one per n)
__global__ void __launch_bounds__(512) scan_sums(float* __restrict__ out)
{
    const int b = blockIdx.x;
    const int n = threadIdx.x;
    ull run = 0ull;
#pragma unroll
    for (int c = 0; c < NCH; c++) {
        ull* p = g_sums + (size_t)(b * NCH + c) * NF + n;
        const ull v = *p;
        *p = run;
        run = add2(run, v);
    }
    if (n == 0) out[NB * SEQ + b * (SEQ + 1) + SEQ] = LOGLIK2;  // loglik last column
}

// ---------------- Kernel D: contraction + outputs ----------------
// grid NB*NCH = 608, 128 threads; cum registers initialized from exclusive base,
// so base-term + local exclusive prefix collapse into one contraction.
__global__ void __launch_bounds__(128) main_contract(
    const float* __restrict__ X,
    const float* __restrict__ alpha,
    float* __restrict__ out)
{
    __shared__ float4 sx[CLEN];
    __shared__ float part[4][CLEN];
    const int bx = blockIdx.x;
    const int b = bx / NCH;
    const int ch = bx - b * NCH;
    const int i0 = ch * CLEN;
    const int clen = (ch == NCH - 1) ? (SEQ - i0) : CLEN;
    const int t = threadIdx.x;

    if (t < clen) {
        const float* xp = X + (size_t)(b * SEQ + i0 + t) * 3;
        sx[t] = make_float4(xp[0], xp[1], xp[2], 0.f);
    }
    const ull w0AC = pk2(g_womg[0 * NF + t], g_womg[0 * NF + t + 256]);
    const ull w1AC = pk2(g_womg[1 * NF + t], g_womg[1 * NF + t + 256]);
    const ull w2AC = pk2(g_womg[2 * NF + t], g_womg[2 * NF + t + 256]);
    const ull w0BD = pk2(g_womg[0 * NF + t + 128], g_womg[0 * NF + t + 384]);
    const ull w1BD = pk2(g_womg[1 * NF + t + 128], g_womg[1 * NF + t + 384]);
    const ull w2BD = pk2(g_womg[2 * NF + t + 128], g_womg[2 * NF + t + 384]);

    const ull* basep = g_sums + (size_t)(b * NCH + ch) * NF;
    ull cumA = basep[t];
    ull cumB = basep[t + 128];
    ull cumC = basep[t + 256];
    ull cumD = basep[t + 384];
    __syncthreads();

#pragma unroll 2
    for (int i = 0; i < clen; i++) {
        const float4 x = sx[i];
        const ull x0 = pk2(x.x, x.x), x1 = pk2(x.y, x.y), x2 = pk2(x.z, x.z);
        const ull thAC = fma2(x2, w2AC, fma2(x1, w1AC, mul2(x0, w0AC)));
        const ull thBD = fma2(x2, w2BD, fma2(x1, w1BD, mul2(x0, w0BD)));
        float tA, tC, tB, tD;
        up2(thAC, tA, tC);
        up2(thBD, tB, tD);
        const ull csA = pk2(fcos(tA), fsin(tA));
        const ull csB = pk2(fcos(tB), fsin(tB));
        const ull csC = pk2(fcos(tC), fsin(tC));
        const ull csD = pk2(fcos(tD), fsin(tD));
        // exclusive prefix: use cum BEFORE updating
        const ull pA = mul2(csA, cumA); cumA = add2(cumA, csA);
        const ull pB = mul2(csB, cumB); cumB = add2(cumB, csB);
        const ull pC = mul2(csC, cumC); cumC = add2(cumC, csC);
        const ull pD = mul2(csD, cumD); cumD = add2(cumD, csD);
        const ull s = add2(add2(pA, pB), add2(pC, pD));
        float lo, hi;
        up2(s, lo, hi);
        float contrib = lo + hi;
#pragma unroll
        for (int o = 16; o > 0; o >>= 1) contrib += __shfl_xor_sync(0xffffffffu, contrib, o);
        if ((t & 31) == 0) part[t >> 5][i] = contrib;
    }
    __syncthreads();

    if (t < clen) {
        const float tot = part[0][t] + part[1][t] + part[2][t] + part[3][t];
        const float ksum = tot * (1.0f / (float)NF);
        const float lam = alpha[0] * ksum + MU_C;
        const int i = i0 + t;
        out[b * SEQ + i] = lam;
        const float x0 = sx[t].x;
        const float ll = (x0 > 0.f ? logf(lam) : 0.f) + LOGLIK2;
        out[NB * SEQ + b * (SEQ + 1) + i] = ll;
    }
}

// ---------------- launch ----------------
extern "C" void kernel_launch(void* const* d_in, const int* in_sizes, int n_in,
                              void* d_out, int out_size)
{
    const float* X     = (const float*)d_in[0];
    const float* noise = (const float*)d_in[1];
    const float* W1    = (const float*)d_in[2];
    const float* b1    = (const float*)d_in[3];
    const float* W2    = (const float*)d_in[4];
    const float* b2    = (const float*)d_in[5];
    const float* Wm    = (const float*)d_in[6];
    const float* alpha = (const float*)d_in[7];
    float* out = (float*)d_out;

    mlp_womg<<<NF, 128>>>(noise, W1, b1, W2, b2, Wm);
    chunk_sums<<<NB * NCH, 128>>>(X);
    scan_sums<<<NB, NF>>>(out);
    main_contract<<<NB * NCH, 128>>>(X, alpha, out);
}

// round 2
// speedup vs baseline: 1.6100x; 1.6100x over previous
#include <cuda_runtime.h>

// ---------------- problem constants ----------------
#define NB   32
#define SEQ  1024
#define NF   512
#define NCH  28      // 28 chunks -> grid 32*28 = 896 blocks (~6/SM, ~1 wave at 75% occ)
#define CLEN 37      // chunks 0..26 have 37 steps, chunk 27 has 25
#define MU_C 10.0f
// loglik2 = -MU*T*(2*pi)^(D-1) = -100 * (2pi)^2
#define LOGLIK2 (-3947.8417604357434f)

typedef unsigned long long ull;

// ---------------- scratch (__device__ globals: no allocation) ----------------
__device__ float g_womg[3 * NF];          // Womg[d][n]
__device__ ull   g_sums[NB * NCH * NF];   // packed (sumC, sumS) per (b, chunk, n); after scan: exclusive base

// ---------------- f32x2 packed helpers (sm_103a) ----------------
static __device__ __forceinline__ ull pk2(float lo, float hi) {
    ull r; asm("mov.b64 %0, {%1, %2};" : "=l"(r) : "f"(lo), "f"(hi)); return r;
}
static __device__ __forceinline__ void up2(ull v, float& lo, float& hi) {
    asm("mov.b64 {%0, %1}, %2;" : "=f"(lo), "=f"(hi) : "l"(v));
}
static __device__ __forceinline__ ull fma2(ull a, ull b, ull c) {
    ull r; asm("fma.rn.f32x2 %0, %1, %2, %3;" : "=l"(r) : "l"(a), "l"(b), "l"(c)); return r;
}
static __device__ __forceinline__ ull mul2(ull a, ull b) {
    ull r; asm("mul.rn.f32x2 %0, %1, %2;" : "=l"(r) : "l"(a), "l"(b)); return r;
}
static __device__ __forceinline__ ull add2(ull a, ull b) {
    ull r; asm("add.rn.f32x2 %0, %1, %2;" : "=l"(r) : "l"(a), "l"(b)); return r;
}
static __device__ __forceinline__ float fsin(float x) {
    float r; asm("sin.approx.f32 %0, %1;" : "=f"(r) : "f"(x)); return r;
}
static __device__ __forceinline__ float fcos(float x) {
    float r; asm("cos.approx.f32 %0, %1;" : "=f"(r) : "f"(x)); return r;
}

// ---------------- Kernel A: fourier MLP -> Womg[3][512] ----------------
// grid 512 (one block per fourier sample n), 128 threads
__global__ void __launch_bounds__(128) mlp_womg(
    const float* __restrict__ noise,  // [512,64]
    const float* __restrict__ W1,     // [64,100]
    const float* __restrict__ b1,     // [100]
    const float* __restrict__ W2,     // [100,256]
    const float* __restrict__ b2,     // [256]
    const float* __restrict__ Wm)     // [256,3]
{
    __shared__ float sn[64];
    __shared__ float sh[100];
    __shared__ float wp[4][3];
    const int n = blockIdx.x;
    const int t = threadIdx.x;

    if (t < 64) sn[t] = noise[n * 64 + t];
    __syncthreads();

    if (t < 100) {
        float a = b1[t];
#pragma unroll 8
        for (int k = 0; k < 64; k++) a += sn[k] * W1[k * 100 + t];
        sh[t] = tanhf(a);
    }
    __syncthreads();

    float a0 = b2[t], a1 = b2[t + 128];
#pragma unroll 4
    for (int h = 0; h < 100; h++) {
        const float hv = sh[h];
        a0 += hv * W2[h * 256 + t];
        a1 += hv * W2[h * 256 + t + 128];
    }
    const float f0 = tanhf(a0);
    const float f1 = tanhf(a1);

    float pd0 = f0 * Wm[t * 3 + 0] + f1 * Wm[(t + 128) * 3 + 0];
    float pd1 = f0 * Wm[t * 3 + 1] + f1 * Wm[(t + 128) * 3 + 1];
    float pd2 = f0 * Wm[t * 3 + 2] + f1 * Wm[(t + 128) * 3 + 2];
#pragma unroll
    for (int o = 16; o > 0; o >>= 1) {
        pd0 += __shfl_xor_sync(0xffffffffu, pd0, o);
        pd1 += __shfl_xor_sync(0xffffffffu, pd1, o);
        pd2 += __shfl_xor_sync(0xffffffffu, pd2, o);
    }
    if ((t & 31) == 0) { wp[t >> 5][0] = pd0; wp[t >> 5][1] = pd1; wp[t >> 5][2] = pd2; }
    __syncthreads();
    if (t == 0) {
#pragma unroll
        for (int d = 0; d < 3; d++)
            g_womg[d * NF + n] = wp[0][d] + wp[1][d] + wp[2][d] + wp[3][d];
    }
}

// ---------------- Kernel B: per-chunk (sumC, sumS) ----------------
// grid NB*NCH = 896, 256 threads, thread owns n in {t, t+256} packed as one f32x2 lane pair
__global__ void __launch_bounds__(256) chunk_sums(const float* __restrict__ X)
{
    __shared__ float4 sx[CLEN];
    const int bx = blockIdx.x;
    const int b = bx / NCH;
    const int ch = bx - b * NCH;
    const int i0 = ch * CLEN;
    const int clen = (ch == NCH - 1) ? (SEQ - i0) : CLEN;
    const int t = threadIdx.x;

    if (t < clen) {
        const float* xp = X + (size_t)(b * SEQ + i0 + t) * 3;
        sx[t] = make_float4(xp[0], xp[1], xp[2], 0.f);
    }
    const ull w0 = pk2(g_womg[0 * NF + t], g_womg[0 * NF + t + 256]);
    const ull w1 = pk2(g_womg[1 * NF + t], g_womg[1 * NF + t + 256]);
    const ull w2 = pk2(g_womg[2 * NF + t], g_womg[2 * NF + t + 256]);
    __syncthreads();

    ull cA = 0ull, cC = 0ull;  // packed (sumC, sumS) for n=t and n=t+256
#pragma unroll 4
    for (int i = 0; i < clen; i++) {
        const float4 x = sx[i];
        const ull x0 = pk2(x.x, x.x), x1 = pk2(x.y, x.y), x2 = pk2(x.z, x.z);
        const ull th = fma2(x2, w2, fma2(x1, w1, mul2(x0, w0)));
        float tA, tC;
        up2(th, tA, tC);
        cA = add2(cA, pk2(fcos(tA), fsin(tA)));
        cC = add2(cC, pk2(fcos(tC), fsin(tC)));
    }
    ull* o = g_sums + (size_t)(b * NCH + ch) * NF;
    o[t]       = cA;
    o[t + 256] = cC;
}

// ---------------- Kernel C: exclusive scan over chunks + loglik tail ----------------
// grid NB, 512 threads (one per n). Preload all chunk aggregates (MLP=NCH), scan in regs.
__global__ void __launch_bounds__(512) scan_sums(float* __restrict__ out)
{
    const int b = blockIdx.x;
    const int n = threadIdx.x;
    ull v[NCH];
    ull* base = g_sums + (size_t)b * NCH * NF + n;
#pragma unroll
    for (int c = 0; c < NCH; c++) v[c] = base[(size_t)c * NF];
    ull run = 0ull;
#pragma unroll
    for (int c = 0; c < NCH; c++) {
        base[(size_t)c * NF] = run;
        run = add2(run, v[c]);
    }
    if (n == 0) out[NB * SEQ + b * (SEQ + 1) + SEQ] = LOGLIK2;  // loglik last column
}

// ---------------- Kernel D: contraction + outputs ----------------
// grid NB*NCH = 896, 256 threads; cum registers initialized from exclusive base,
// so base-term + local exclusive prefix collapse into one contraction.
__global__ void __launch_bounds__(256) main_contract(
    const float* __restrict__ X,
    const float* __restrict__ alpha,
    float* __restrict__ out)
{
    __shared__ float4 sx[CLEN];
    __shared__ float part[CLEN * 9];   // 8 warps + pad
    const int bx = blockIdx.x;
    const int b = bx / NCH;
    const int ch = bx - b * NCH;
    const int i0 = ch * CLEN;
    const int clen = (ch == NCH - 1) ? (SEQ - i0) : CLEN;
    const int t = threadIdx.x;
    const int w = t >> 5;

    if (t < clen) {
        const float* xp = X + (size_t)(b * SEQ + i0 + t) * 3;
        sx[t] = make_float4(xp[0], xp[1], xp[2], 0.f);
    }
    const ull w0 = pk2(g_womg[0 * NF + t], g_womg[0 * NF + t + 256]);
    const ull w1 = pk2(g_womg[1 * NF + t], g_womg[1 * NF + t + 256]);
    const ull w2 = pk2(g_womg[2 * NF + t], g_womg[2 * NF + t + 256]);

    const ull* basep = g_sums + (size_t)(b * NCH + ch) * NF;
    ull cumA = basep[t];
    ull cumC = basep[t + 256];
    __syncthreads();

#pragma unroll 4
    for (int i = 0; i < clen; i++) {
        const float4 x = sx[i];
        const ull x0 = pk2(x.x, x.x), x1 = pk2(x.y, x.y), x2 = pk2(x.z, x.z);
        const ull th = fma2(x2, w2, fma2(x1, w1, mul2(x0, w0)));
        float tA, tC;
        up2(th, tA, tC);
        const ull csA = pk2(fcos(tA), fsin(tA));
        const ull csC = pk2(fcos(tC), fsin(tC));
        // exclusive prefix: use cum BEFORE updating
        const ull pA = mul2(csA, cumA); cumA = add2(cumA, csA);
        const ull pC = mul2(csC, cumC); cumC = add2(cumC, csC);
        const ull s = add2(pA, pC);
        float lo, hi;
        up2(s, lo, hi);
        float contrib = lo + hi;
#pragma unroll
        for (int o = 16; o > 0; o >>= 1) contrib += __shfl_xor_sync(0xffffffffu, contrib, o);
        if ((t & 31) == 0) part[i * 9 + w] = contrib;
    }
    __syncthreads();

    if (t < clen) {
        float tot = 0.f;
#pragma unroll
        for (int ww = 0; ww < 8; ww++) tot += part[t * 9 + ww];
        const float ksum = tot * (1.0f / (float)NF);
        const float lam = alpha[0] * ksum + MU_C;
        const int i = i0 + t;
        out[b * SEQ + i] = lam;
        const float x0 = sx[t].x;
        const float ll = (x0 > 0.f ? logf(lam) : 0.f) + LOGLIK2;
        out[NB * SEQ + b * (SEQ + 1) + i] = ll;
    }
}

// ---------------- launch ----------------
extern "C" void kernel_launch(void* const* d_in, const int* in_sizes, int n_in,
                              void* d_out, int out_size)
{
    const float* X     = (const float*)d_in[0];
    const float* noise = (const float*)d_in[1];
    const float* W1    = (const float*)d_in[2];
    const float* b1    = (const float*)d_in[3];
    const float* W2    = (const float*)d_in[4];
    const float* b2    = (const float*)d_in[5];
    const float* Wm    = (const float*)d_in[6];
    const float* alpha = (const float*)d_in[7];
    float* out = (float*)d_out;

    mlp_womg<<<NF, 128>>>(noise, W1, b1, W2, b2, Wm);
    chunk_sums<<<NB * NCH, 256>>>(X);
    scan_sums<<<NB, NF>>>(out);
    main_contract<<<NB * NCH, 256>>>(X, alpha, out);
}